// round 3
// baseline (speedup 1.0000x reference)
#include <cuda_runtime.h>

#define NN   20000
#define BB   4
#define DD   32
#define OUTF 64
#define SS   2
#define EE   640000
#define MM   7            // metrics
#define FF   128          // DD*BB
#define KK   224          // DD*MM
#define CAP  96           // padded-CSR slots per row (P(deg>=96) ~ 4e-20)

// ---------------- device scratch (no allocs allowed) ----------------
__device__ float g_x[MM][NN * FF];                  // 7 x 10.24 MB
__device__ int   g_cnt[SS][NN];
__device__ __align__(16) int2 g_edges[SS][NN * CAP]; // padded CSR: (src, val_bits)

// ---------------- f32x2 packed-FMA helpers ------------------------------------
__device__ __forceinline__ unsigned long long pk2(float lo, float hi) {
    unsigned long long r;
    asm("mov.b64 %0, {%1, %2};" : "=l"(r) : "f"(lo), "f"(hi));
    return r;
}
__device__ __forceinline__ void upk2(float& lo, float& hi, unsigned long long v) {
    asm("mov.b64 {%0, %1}, %2;" : "=f"(lo), "=f"(hi) : "l"(v));
}
__device__ __forceinline__ unsigned long long ffma2(unsigned long long a,
                                                    unsigned long long b,
                                                    unsigned long long c) {
    unsigned long long d;
    asm("fma.rn.f32x2 %0, %1, %2, %3;" : "=l"(d) : "l"(a), "l"(b), "l"(c));
    return d;
}

// ---------------- prep: x0 transpose + counter zero (fused) -------------------
__global__ void k_prep(const float* __restrict__ in) {
    int idx = blockIdx.x * blockDim.x + threadIdx.x;
    if (idx < SS * NN) ((int*)g_cnt)[idx] = 0;
    if (idx >= NN * FF) return;
    int n = idx >> 7;
    int r = idx & 127;
    int d = r >> 2, b = r & 3;
    g_x[0][idx] = in[((size_t)b * NN + n) * DD + d];
}

// ---------------- padded-CSR build: one atomic slot-grab per edge -------------
__global__ void k_scatter(const int* __restrict__ src, const int* __restrict__ dst,
                          const float* __restrict__ vals) {
    int s   = blockIdx.y;
    int idx = blockIdx.x * blockDim.x + threadIdx.x;
    if (idx >= EE) return;
    int d   = dst[s * EE + idx];
    int pos = atomicAdd(&g_cnt[s][d], 1);
    if (pos < CAP)
        g_edges[s][d * CAP + pos] =
            make_int2(src[s * EE + idx], __float_as_int(vals[s * EE + idx]));
}

// ---------------- SPMM: one warp per destination row, lane owns a float4 ------
// out = spmm(in) if ci<0 else 2*spmm(in)-c
__device__ __forceinline__ void spmm_row(int ii, int ci, int oi, int s,
                                         int gw, int lane) {
    const float* __restrict__ xin = g_x[ii];
    float* __restrict__ xout      = g_x[oi];
    int cnt = g_cnt[s][gw];
    cnt = cnt > CAP ? CAP : cnt;
    int beg = gw * CAP;                 // always 16B-aligned (CAP even)
    int end = beg + cnt;
    const int2* __restrict__ ed = g_edges[s];
    float ax = 0.f, ay = 0.f, az = 0.f, aw = 0.f;
    int e = beg;
    int f0 = lane * 4;
    for (; e + 8 <= end; e += 8) {
        int4 p0 = *(const int4*)(ed + e);
        int4 p1 = *(const int4*)(ed + e + 2);
        int4 p2 = *(const int4*)(ed + e + 4);
        int4 p3 = *(const int4*)(ed + e + 6);
        float4 x0 = *(const float4*)(xin + p0.x * FF + f0);
        float4 x1 = *(const float4*)(xin + p0.z * FF + f0);
        float4 x2 = *(const float4*)(xin + p1.x * FF + f0);
        float4 x3 = *(const float4*)(xin + p1.z * FF + f0);
        float4 x4 = *(const float4*)(xin + p2.x * FF + f0);
        float4 x5 = *(const float4*)(xin + p2.z * FF + f0);
        float4 x6 = *(const float4*)(xin + p3.x * FF + f0);
        float4 x7 = *(const float4*)(xin + p3.z * FF + f0);
        float v0 = __int_as_float(p0.y), v1 = __int_as_float(p0.w);
        float v2 = __int_as_float(p1.y), v3 = __int_as_float(p1.w);
        float v4 = __int_as_float(p2.y), v5 = __int_as_float(p2.w);
        float v6 = __int_as_float(p3.y), v7 = __int_as_float(p3.w);
        ax = fmaf(v0, x0.x, ax); ay = fmaf(v0, x0.y, ay); az = fmaf(v0, x0.z, az); aw = fmaf(v0, x0.w, aw);
        ax = fmaf(v1, x1.x, ax); ay = fmaf(v1, x1.y, ay); az = fmaf(v1, x1.z, az); aw = fmaf(v1, x1.w, aw);
        ax = fmaf(v2, x2.x, ax); ay = fmaf(v2, x2.y, ay); az = fmaf(v2, x2.z, az); aw = fmaf(v2, x2.w, aw);
        ax = fmaf(v3, x3.x, ax); ay = fmaf(v3, x3.y, ay); az = fmaf(v3, x3.z, az); aw = fmaf(v3, x3.w, aw);
        ax = fmaf(v4, x4.x, ax); ay = fmaf(v4, x4.y, ay); az = fmaf(v4, x4.z, az); aw = fmaf(v4, x4.w, aw);
        ax = fmaf(v5, x5.x, ax); ay = fmaf(v5, x5.y, ay); az = fmaf(v5, x5.z, az); aw = fmaf(v5, x5.w, aw);
        ax = fmaf(v6, x6.x, ax); ay = fmaf(v6, x6.y, ay); az = fmaf(v6, x6.z, az); aw = fmaf(v6, x6.w, aw);
        ax = fmaf(v7, x7.x, ax); ay = fmaf(v7, x7.y, ay); az = fmaf(v7, x7.z, az); aw = fmaf(v7, x7.w, aw);
    }
    for (; e < end; e++) {
        int2 e0  = ed[e];
        float4 x0 = *(const float4*)(xin + e0.x * FF + f0);
        float v0 = __int_as_float(e0.y);
        ax = fmaf(v0, x0.x, ax); ay = fmaf(v0, x0.y, ay);
        az = fmaf(v0, x0.z, az); aw = fmaf(v0, x0.w, aw);
    }
    float4 r;
    if (ci >= 0) {
        const float* __restrict__ cin = g_x[ci];
        float4 c = *(const float4*)(cin + gw * FF + f0);
        r.x = 2.f * ax - c.x; r.y = 2.f * ay - c.y;
        r.z = 2.f * az - c.z; r.w = 2.f * aw - c.w;
    } else {
        r.x = ax; r.y = ay; r.z = az; r.w = aw;
    }
    *(float4*)(xout + gw * FF + f0) = r;
}

__global__ void __launch_bounds__(256) k_spmm(int ii, int ci, int oi, int s) {
    int gw   = (blockIdx.x * blockDim.x + threadIdx.x) >> 5;
    int lane = threadIdx.x & 31;
    if (gw >= NN) return;
    spmm_row(ii, ci, oi, s, gw, lane);
}

// dual launch: blockIdx.y selects between two independent SPMM jobs
__global__ void __launch_bounds__(256) k_spmm2(int ii0, int ci0, int oi0, int s0,
                                               int ii1, int ci1, int oi1, int s1) {
    int gw   = (blockIdx.x * blockDim.x + threadIdx.x) >> 5;
    int lane = threadIdx.x & 31;
    if (gw >= NN) return;
    if (blockIdx.y == 0) spmm_row(ii0, ci0, oi0, s0, gw, lane);
    else                 spmm_row(ii1, ci1, oi1, s1, gw, lane);
}

// ---------------- final projection (f32x2 packed FMA, 2 n-tiles per CTA) ------
// y[b,n,o] = sum_{d,m} xs[m][n][d*4+b] * W[o][d*7+m] + bias[o]
#define TN        16                       // n-rows per subtile
#define NT        2                        // subtiles per CTA (W reuse)
#define XPAD      132                      // 128 + 4-float pad
#define GEMM_SMEM ((KK * OUTF + MM * TN * XPAD + OUTF) * 4)

__global__ void __launch_bounds__(256) k_gemm(const float* __restrict__ W,
                                              const float* __restrict__ bias,
                                              float* __restrict__ out) {
    extern __shared__ float sm[];
    float* Wt  = sm;                        // [KK][OUTF], transposed (o contiguous)
    float* xsm = sm + KK * OUTF;            // [MM][TN][XPAD]
    float* bsm = xsm + MM * TN * XPAD;      // [OUTF]
    int tid = threadIdx.x;

    for (int idx = tid; idx < KK * OUTF; idx += 256) {
        int o = idx & 63, k = idx >> 6;
        Wt[idx] = W[o * KK + k];
    }
    if (tid < OUTF) bsm[tid] = bias[tid];

    int r  = tid >> 2;                // 0..63 : (nl, b) row
    int q  = tid & 3;                 // output group: o = q*16 .. q*16+15
    int nl = r >> 2, b = r & 3;
    const float* xrow = xsm + nl * XPAD + b;

    for (int t = 0; t < NT; t++) {
        int n0 = (blockIdx.x * NT + t) * TN;
        for (int idx = tid; idx < MM * TN * FF; idx += 256) {
            int m   = idx / (TN * FF);
            int rem = idx - m * (TN * FF);
            int nli = rem >> 7, f = rem & 127;
            xsm[m * (TN * XPAD) + nli * XPAD + f] = g_x[m][(n0 + nli) * FF + f];
        }
        __syncthreads();

        unsigned long long acc[8];    // 8 f32x2 pairs = 16 outputs
#pragma unroll
        for (int j = 0; j < 8; j++) acc[j] = 0ull;

#pragma unroll 2
        for (int d = 0; d < DD; d++) {
#pragma unroll
            for (int m = 0; m < MM; m++) {
                float xv = xrow[m * (TN * XPAD) + d * 4];
                unsigned long long xp = pk2(xv, xv);
                const ulonglong2* w2 = (const ulonglong2*)(Wt + (d * MM + m) * OUTF + q * 16);
                ulonglong2 wa = w2[0], wb = w2[1], wc = w2[2], wd = w2[3];
                acc[0] = ffma2(xp, wa.x, acc[0]); acc[1] = ffma2(xp, wa.y, acc[1]);
                acc[2] = ffma2(xp, wb.x, acc[2]); acc[3] = ffma2(xp, wb.y, acc[3]);
                acc[4] = ffma2(xp, wc.x, acc[4]); acc[5] = ffma2(xp, wc.y, acc[5]);
                acc[6] = ffma2(xp, wd.x, acc[6]); acc[7] = ffma2(xp, wd.y, acc[7]);
            }
        }

        int n = n0 + nl;
        float* op = out + ((size_t)b * NN + n) * OUTF + q * 16;
#pragma unroll
        for (int j = 0; j < 4; j++) {
            float a0, a1, a2, a3;
            upk2(a0, a1, acc[j * 2]);
            upk2(a2, a3, acc[j * 2 + 1]);
            float4 o4;
            o4.x = a0 + bsm[q * 16 + j * 4 + 0];
            o4.y = a1 + bsm[q * 16 + j * 4 + 1];
            o4.z = a2 + bsm[q * 16 + j * 4 + 2];
            o4.w = a3 + bsm[q * 16 + j * 4 + 3];
            *(float4*)(op + j * 4) = o4;
        }
        __syncthreads();
    }
}

// ---------------- launch ----------------
extern "C" void kernel_launch(void* const* d_in, const int* in_sizes, int n_in,
                              void* d_out, int out_size) {
    const float* inputs = (const float*)d_in[0];
    const float* evals  = (const float*)d_in[1];
    const float* W      = (const float*)d_in[2];
    const float* bias   = (const float*)d_in[3];
    const int*   esrc   = (const int*)d_in[4];
    const int*   edst   = (const int*)d_in[5];
    float* out = (float*)d_out;

    // (1) x0 build + counter zero (fused)
    k_prep<<<(NN * FF + 255) / 256, 256>>>(inputs);

    // (2) padded-CSR build for both supports
    dim3 ge((EE + 255) / 256, SS);
    k_scatter<<<ge, 256>>>(esrc, edst, evals);

    // (3..7) Chebyshev recurrence (faithful to reference aliasing)
    const int spmm_grid = (NN * 32 + 255) / 256;   // 1 warp per row
    k_spmm<<<spmm_grid, 256>>>(0, -1, 1, 0);                 // (3) xs1 = A0 x0
    k_spmm<<<spmm_grid, 256>>>(1,  0, 2, 0);                 // (4) xs2 = 2 A0 xs1 - xs0  [profiled slot]
    dim3 gd(spmm_grid, 2);
    k_spmm2<<<gd, 256>>>(2, 1, 3, 0,   2, -1, 4, 1);         // (5) xs3 ∥ xs4
    k_spmm<<<spmm_grid, 256>>>(4,  2, 5, 1);                 // (6) xs5 = 2 A1 xs4 - xs2
    k_spmm<<<spmm_grid, 256>>>(5,  4, 6, 1);                 // (7) xs6 = 2 A1 xs5 - xs4

    // (8) projection
    cudaFuncSetAttribute(k_gemm, cudaFuncAttributeMaxDynamicSharedMemorySize, GEMM_SMEM);
    k_gemm<<<NN / (TN * NT), 256, GEMM_SMEM>>>(W, bias, out);
}

// round 4
// speedup vs baseline: 2.1139x; 2.1139x over previous
#include <cuda_runtime.h>

#define NN   20000
#define BB   4
#define DD   32
#define OUTF 64
#define SS   2
#define EE   640000
#define MM   7            // metrics
#define FF   128          // DD*BB
#define KK   224          // DD*MM

// ---------------- device scratch (no allocs allowed) ----------------
__device__ float g_x[MM][NN * FF];          // 7 x 10.24 MB
__device__ int   g_cnt[SS][NN];
__device__ int   g_fill[SS][NN];
__device__ int   g_rowptr[SS][NN + 1];
__device__ __align__(16) int2 g_edges[SS][EE];  // dense CSR: (src, val_bits)

// ---------------- f32x2 packed-FMA helpers ------------------------------------
__device__ __forceinline__ unsigned long long pk2(float lo, float hi) {
    unsigned long long r;
    asm("mov.b64 %0, {%1, %2};" : "=l"(r) : "f"(lo), "f"(hi));
    return r;
}
__device__ __forceinline__ void upk2(float& lo, float& hi, unsigned long long v) {
    asm("mov.b64 {%0, %1}, %2;" : "=f"(lo), "=f"(hi) : "l"(v));
}
__device__ __forceinline__ unsigned long long ffma2(unsigned long long a,
                                                    unsigned long long b,
                                                    unsigned long long c) {
    unsigned long long d;
    asm("fma.rn.f32x2 %0, %1, %2, %3;" : "=l"(d) : "l"(a), "l"(b), "l"(c));
    return d;
}

// ---------------- prep: x0 transpose + counter zero (fused) -------------------
__global__ void k_prep(const float* __restrict__ in) {
    int idx = blockIdx.x * blockDim.x + threadIdx.x;
    if (idx < SS * NN) ((int*)g_cnt)[idx] = 0;
    if (idx >= NN * FF) return;
    int n = idx >> 7;
    int r = idx & 127;
    int d = r >> 2, b = r & 3;
    g_x[0][idx] = in[((size_t)b * NN + n) * DD + d];
}

__global__ void k_hist(const int* __restrict__ dst) {
    int s   = blockIdx.y;
    int idx = blockIdx.x * blockDim.x + threadIdx.x;
    if (idx < EE) atomicAdd(&g_cnt[s][dst[s * EE + idx]], 1);
}

// one block of 1024 per support: thread-coarsened + warp-shuffle scan
#define SC 20   // elements per thread; 1024*20 >= 20000
__global__ void __launch_bounds__(1024) k_scan() {
    int s = blockIdx.x, t = threadIdx.x;
    int lane = t & 31, warp = t >> 5;
    int base = t * SC;
    int v[SC];
    int sum = 0;
#pragma unroll
    for (int i = 0; i < SC; i++) {
        v[i] = (base + i < NN) ? g_cnt[s][base + i] : 0;
        sum += v[i];
    }
    int inc = sum;
#pragma unroll
    for (int off = 1; off < 32; off <<= 1) {
        int u = __shfl_up_sync(0xffffffffu, inc, off);
        if (lane >= off) inc += u;
    }
    __shared__ int wtot[32];
    if (lane == 31) wtot[warp] = inc;
    __syncthreads();
    if (warp == 0) {
        int w = wtot[lane];
        int wi = w;
#pragma unroll
        for (int off = 1; off < 32; off <<= 1) {
            int u = __shfl_up_sync(0xffffffffu, wi, off);
            if (lane >= off) wi += u;
        }
        wtot[lane] = wi - w;    // exclusive
    }
    __syncthreads();
    int run = wtot[warp] + (inc - sum);   // exclusive prefix for this thread
#pragma unroll
    for (int i = 0; i < SC; i++) {
        if (base + i < NN) { g_rowptr[s][base + i] = run; g_fill[s][base + i] = run; }
        run += v[i];
    }
    if (t == 1023) g_rowptr[s][NN] = run;
}

__global__ void k_scatter(const int* __restrict__ src, const int* __restrict__ dst,
                          const float* __restrict__ vals) {
    int s   = blockIdx.y;
    int idx = blockIdx.x * blockDim.x + threadIdx.x;
    if (idx >= EE) return;
    int d   = dst[s * EE + idx];
    int pos = atomicAdd(&g_fill[s][d], 1);
    g_edges[s][pos] = make_int2(src[s * EE + idx], __float_as_int(vals[s * EE + idx]));
}

// ---------------- SPMM: one warp per destination row, lane owns a float4 ------
// out = spmm(in) if ci<0 else 2*spmm(in)-c
__device__ __forceinline__ void spmm_row(int ii, int ci, int oi, int s,
                                         int gw, int lane) {
    const float* __restrict__ xin = g_x[ii];
    float* __restrict__ xout      = g_x[oi];
    int beg = g_rowptr[s][gw], end = g_rowptr[s][gw + 1];
    const int2* __restrict__ ed = g_edges[s];
    float ax = 0.f, ay = 0.f, az = 0.f, aw = 0.f;
    int e = beg;
    int f0 = lane * 4;
    // peel to even e so int4 (2-edge) loads are 16B aligned
    if (e < end && (e & 1)) {
        int2 e0 = ed[e];
        float4 x0 = *(const float4*)(xin + e0.x * FF + f0);
        float v0 = __int_as_float(e0.y);
        ax = fmaf(v0, x0.x, ax); ay = fmaf(v0, x0.y, ay);
        az = fmaf(v0, x0.z, az); aw = fmaf(v0, x0.w, aw);
        e++;
    }
    for (; e + 8 <= end; e += 8) {
        int4 p0 = *(const int4*)(ed + e);
        int4 p1 = *(const int4*)(ed + e + 2);
        int4 p2 = *(const int4*)(ed + e + 4);
        int4 p3 = *(const int4*)(ed + e + 6);
        float4 x0 = *(const float4*)(xin + p0.x * FF + f0);
        float4 x1 = *(const float4*)(xin + p0.z * FF + f0);
        float4 x2 = *(const float4*)(xin + p1.x * FF + f0);
        float4 x3 = *(const float4*)(xin + p1.z * FF + f0);
        float4 x4 = *(const float4*)(xin + p2.x * FF + f0);
        float4 x5 = *(const float4*)(xin + p2.z * FF + f0);
        float4 x6 = *(const float4*)(xin + p3.x * FF + f0);
        float4 x7 = *(const float4*)(xin + p3.z * FF + f0);
        float v0 = __int_as_float(p0.y), v1 = __int_as_float(p0.w);
        float v2 = __int_as_float(p1.y), v3 = __int_as_float(p1.w);
        float v4 = __int_as_float(p2.y), v5 = __int_as_float(p2.w);
        float v6 = __int_as_float(p3.y), v7 = __int_as_float(p3.w);
        ax = fmaf(v0, x0.x, ax); ay = fmaf(v0, x0.y, ay); az = fmaf(v0, x0.z, az); aw = fmaf(v0, x0.w, aw);
        ax = fmaf(v1, x1.x, ax); ay = fmaf(v1, x1.y, ay); az = fmaf(v1, x1.z, az); aw = fmaf(v1, x1.w, aw);
        ax = fmaf(v2, x2.x, ax); ay = fmaf(v2, x2.y, ay); az = fmaf(v2, x2.z, az); aw = fmaf(v2, x2.w, aw);
        ax = fmaf(v3, x3.x, ax); ay = fmaf(v3, x3.y, ay); az = fmaf(v3, x3.z, az); aw = fmaf(v3, x3.w, aw);
        ax = fmaf(v4, x4.x, ax); ay = fmaf(v4, x4.y, ay); az = fmaf(v4, x4.z, az); aw = fmaf(v4, x4.w, aw);
        ax = fmaf(v5, x5.x, ax); ay = fmaf(v5, x5.y, ay); az = fmaf(v5, x5.z, az); aw = fmaf(v5, x5.w, aw);
        ax = fmaf(v6, x6.x, ax); ay = fmaf(v6, x6.y, ay); az = fmaf(v6, x6.z, az); aw = fmaf(v6, x6.w, aw);
        ax = fmaf(v7, x7.x, ax); ay = fmaf(v7, x7.y, ay); az = fmaf(v7, x7.z, az); aw = fmaf(v7, x7.w, aw);
    }
    for (; e < end; e++) {
        int2 e0  = ed[e];
        float4 x0 = *(const float4*)(xin + e0.x * FF + f0);
        float v0 = __int_as_float(e0.y);
        ax = fmaf(v0, x0.x, ax); ay = fmaf(v0, x0.y, ay);
        az = fmaf(v0, x0.z, az); aw = fmaf(v0, x0.w, aw);
    }
    float4 r;
    if (ci >= 0) {
        const float* __restrict__ cin = g_x[ci];
        float4 c = *(const float4*)(cin + gw * FF + f0);
        r.x = 2.f * ax - c.x; r.y = 2.f * ay - c.y;
        r.z = 2.f * az - c.z; r.w = 2.f * aw - c.w;
    } else {
        r.x = ax; r.y = ay; r.z = az; r.w = aw;
    }
    *(float4*)(xout + gw * FF + f0) = r;
}

__global__ void __launch_bounds__(256) k_spmm(int ii, int ci, int oi, int s) {
    int gw   = (blockIdx.x * blockDim.x + threadIdx.x) >> 5;
    int lane = threadIdx.x & 31;
    if (gw >= NN) return;
    spmm_row(ii, ci, oi, s, gw, lane);
}

// dual launch: blockIdx.y selects between two independent SPMM jobs
__global__ void __launch_bounds__(256) k_spmm2(int ii0, int ci0, int oi0, int s0,
                                               int ii1, int ci1, int oi1, int s1) {
    int gw   = (blockIdx.x * blockDim.x + threadIdx.x) >> 5;
    int lane = threadIdx.x & 31;
    if (gw >= NN) return;
    if (blockIdx.y == 0) spmm_row(ii0, ci0, oi0, s0, gw, lane);
    else                 spmm_row(ii1, ci1, oi1, s1, gw, lane);
}

// ---------------- final projection: 2 rows/thread, halved W LDS traffic -------
// y[b,n,o] = sum_{d,m} xs[m][n][d*4+b] * W[o][d*7+m] + bias[o]
#define TNG       32                       // n-rows per CTA
#define XPAD      132                      // 128 + 4-float pad (16B-aligned rows)
#define GEMM_SMEM ((KK * OUTF + MM * TNG * XPAD + OUTF) * 4)   // 175,872 B

__global__ void __launch_bounds__(256) k_gemm(const float* __restrict__ W,
                                              const float* __restrict__ bias,
                                              float* __restrict__ out) {
    extern __shared__ float sm[];
    float* Wt  = sm;                        // [KK][OUTF], transposed (o contiguous)
    float* xsm = sm + KK * OUTF;            // [MM][TNG][XPAD]
    float* bsm = xsm + MM * TNG * XPAD;     // [OUTF]
    int tid = threadIdx.x;

    // W transpose: float4 reads along k, scalar STS
    for (int idx = tid; idx < KK * OUTF / 4; idx += 256) {
        int o  = idx / (KK / 4);
        int kq = idx - o * (KK / 4);
        float4 w = *(const float4*)(W + o * KK + kq * 4);
        Wt[(kq * 4 + 0) * OUTF + o] = w.x;
        Wt[(kq * 4 + 1) * OUTF + o] = w.y;
        Wt[(kq * 4 + 2) * OUTF + o] = w.z;
        Wt[(kq * 4 + 3) * OUTF + o] = w.w;
    }
    if (tid < OUTF) bsm[tid] = bias[tid];

    // stage x tile with float4 loads
    int n0 = blockIdx.x * TNG;
    for (int idx = tid; idx < MM * TNG * FF / 4; idx += 256) {
        int m   = idx / (TNG * FF / 4);
        int rem = idx - m * (TNG * FF / 4);
        int nl  = rem >> 5;                 // FF/4 = 32 float4 per row
        int f4  = rem & 31;
        float4 v = *(const float4*)(&g_x[m][(n0 + nl) * FF + f4 * 4]);
        *(float4*)(&xsm[m * (TNG * XPAD) + nl * XPAD + f4 * 4]) = v;
    }
    __syncthreads();

    int q     = tid & 3;                    // output group: o = q*16..q*16+15
    int rowid = tid >> 2;                   // 0..63
    int b     = rowid & 3;
    int nl0   = rowid >> 2;                 // 0..15 ; second row = nl0+16
    const float* xr0 = xsm + nl0 * XPAD + b;
    const float* xr1 = xsm + (nl0 + 16) * XPAD + b;

    unsigned long long acc[16];             // rows0/1 x 8 f32x2 pairs
#pragma unroll
    for (int j = 0; j < 16; j++) acc[j] = 0ull;

#pragma unroll 2
    for (int d = 0; d < DD; d++) {
#pragma unroll
        for (int m = 0; m < MM; m++) {
            int xoff = m * (TNG * XPAD) + d * 4;
            float xv0 = xr0[xoff];
            float xv1 = xr1[xoff];
            unsigned long long xp0 = pk2(xv0, xv0);
            unsigned long long xp1 = pk2(xv1, xv1);
            const ulonglong2* w2 = (const ulonglong2*)(Wt + (d * MM + m) * OUTF + q * 16);
            ulonglong2 wa = w2[0], wb = w2[1], wc = w2[2], wd = w2[3];
            acc[0]  = ffma2(xp0, wa.x, acc[0]);  acc[1]  = ffma2(xp0, wa.y, acc[1]);
            acc[2]  = ffma2(xp0, wb.x, acc[2]);  acc[3]  = ffma2(xp0, wb.y, acc[3]);
            acc[4]  = ffma2(xp0, wc.x, acc[4]);  acc[5]  = ffma2(xp0, wc.y, acc[5]);
            acc[6]  = ffma2(xp0, wd.x, acc[6]);  acc[7]  = ffma2(xp0, wd.y, acc[7]);
            acc[8]  = ffma2(xp1, wa.x, acc[8]);  acc[9]  = ffma2(xp1, wa.y, acc[9]);
            acc[10] = ffma2(xp1, wb.x, acc[10]); acc[11] = ffma2(xp1, wb.y, acc[11]);
            acc[12] = ffma2(xp1, wc.x, acc[12]); acc[13] = ffma2(xp1, wc.y, acc[13]);
            acc[14] = ffma2(xp1, wd.x, acc[14]); acc[15] = ffma2(xp1, wd.y, acc[15]);
        }
    }

#pragma unroll
    for (int rr = 0; rr < 2; rr++) {
        int n = n0 + nl0 + rr * 16;
        float* op = out + ((size_t)b * NN + n) * OUTF + q * 16;
#pragma unroll
        for (int j = 0; j < 4; j++) {
            float a0, a1, a2, a3;
            upk2(a0, a1, acc[rr * 8 + j * 2]);
            upk2(a2, a3, acc[rr * 8 + j * 2 + 1]);
            float4 o4;
            o4.x = a0 + bsm[q * 16 + j * 4 + 0];
            o4.y = a1 + bsm[q * 16 + j * 4 + 1];
            o4.z = a2 + bsm[q * 16 + j * 4 + 2];
            o4.w = a3 + bsm[q * 16 + j * 4 + 3];
            *(float4*)(op + j * 4) = o4;
        }
    }
}

// ---------------- launch ----------------
extern "C" void kernel_launch(void* const* d_in, const int* in_sizes, int n_in,
                              void* d_out, int out_size) {
    const float* inputs = (const float*)d_in[0];
    const float* evals  = (const float*)d_in[1];
    const float* W      = (const float*)d_in[2];
    const float* bias   = (const float*)d_in[3];
    const int*   esrc   = (const int*)d_in[4];
    const int*   edst   = (const int*)d_in[5];
    float* out = (float*)d_out;

    // x0 build + counter zero (fused)
    k_prep<<<(NN * FF + 255) / 256, 256>>>(inputs);

    // dense CSR build for both supports
    dim3 ge((EE + 255) / 256, SS);
    k_hist<<<ge, 256>>>(edst);
    k_scan<<<SS, 1024>>>();
    k_scatter<<<ge, 256>>>(esrc, edst, evals);

    // Chebyshev recurrence (faithful to reference aliasing)
    const int spmm_grid = (NN * 32 + 255) / 256;   // 1 warp per row
    k_spmm<<<spmm_grid, 256>>>(0, -1, 1, 0);                 // xs1 = A0 x0
    k_spmm<<<spmm_grid, 256>>>(1,  0, 2, 0);                 // xs2 = 2 A0 xs1 - xs0
    dim3 gd(spmm_grid, 2);
    k_spmm2<<<gd, 256>>>(2, 1, 3, 0,   2, -1, 4, 1);         // xs3 ∥ xs4
    k_spmm<<<spmm_grid, 256>>>(4,  2, 5, 1);                 // xs5 = 2 A1 xs4 - xs2
    k_spmm<<<spmm_grid, 256>>>(5,  4, 6, 1);                 // xs6 = 2 A1 xs5 - xs4

    // projection (2 rows/thread, TNG=32)
    cudaFuncSetAttribute(k_gemm, cudaFuncAttributeMaxDynamicSharedMemorySize, GEMM_SMEM);
    k_gemm<<<NN / TNG, 256, GEMM_SMEM>>>(W, bias, out);
}

// round 5
// speedup vs baseline: 2.8439x; 1.3453x over previous
#include <cuda_runtime.h>
#include <cuda_fp16.h>

#define NN   20000
#define BB   4
#define DD   32
#define OUTF 64
#define SS   2
#define EE   640000
#define MM   7            // metrics
#define FF   128          // DD*BB
#define KK   224          // DD*MM

// ---------------- device scratch (no allocs allowed) ----------------
__device__ __half g_xh[MM][NN * FF];            // 7 x 5.12 MB (fp16 storage)
__device__ int   g_cnt[SS][NN];
__device__ int   g_fill[SS][NN];
__device__ int   g_rowptr[SS][NN + 1];
__device__ __align__(16) int2 g_edges[SS][EE];  // dense CSR: (src, val_bits)

// ---------------- f32x2 packed-FMA helpers ------------------------------------
__device__ __forceinline__ unsigned long long pk2(float lo, float hi) {
    unsigned long long r;
    asm("mov.b64 %0, {%1, %2};" : "=l"(r) : "f"(lo), "f"(hi));
    return r;
}
__device__ __forceinline__ void upk2(float& lo, float& hi, unsigned long long v) {
    asm("mov.b64 {%0, %1}, %2;" : "=f"(lo), "=f"(hi) : "l"(v));
}
__device__ __forceinline__ unsigned long long ffma2(unsigned long long a,
                                                    unsigned long long b,
                                                    unsigned long long c) {
    unsigned long long d;
    asm("fma.rn.f32x2 %0, %1, %2, %3;" : "=l"(d) : "l"(a), "l"(b), "l"(c));
    return d;
}

// ---------------- prep: x0 transpose->fp16 + counter zero (fused) -------------
// one thread per (n, d): gathers b=0..3, packs 4 halves
__global__ void k_prep(const float* __restrict__ in) {
    int idx = blockIdx.x * blockDim.x + threadIdx.x;
    if (idx < SS * NN) ((int*)g_cnt)[idx] = 0;
    if (idx >= NN * DD) return;
    int n = idx >> 5, d = idx & 31;
    float v0 = in[((size_t)0 * NN + n) * DD + d];
    float v1 = in[((size_t)1 * NN + n) * DD + d];
    float v2 = in[((size_t)2 * NN + n) * DD + d];
    float v3 = in[((size_t)3 * NN + n) * DD + d];
    __half2 h01 = __floats2half2_rn(v0, v1);
    __half2 h23 = __floats2half2_rn(v2, v3);
    __half2* p = (__half2*)&g_xh[0][n * FF + d * 4];
    p[0] = h01; p[1] = h23;
}

__global__ void k_hist(const int* __restrict__ dst) {
    int s   = blockIdx.y;
    int idx = blockIdx.x * blockDim.x + threadIdx.x;
    if (idx >= EE / 2) return;
    int2 d2 = *(const int2*)(dst + s * EE + idx * 2);
    atomicAdd(&g_cnt[s][d2.x], 1);
    atomicAdd(&g_cnt[s][d2.y], 1);
}

// one block of 1024 per support: thread-coarsened + warp-shuffle scan
#define SC 20
__global__ void __launch_bounds__(1024) k_scan() {
    int s = blockIdx.x, t = threadIdx.x;
    int lane = t & 31, warp = t >> 5;
    int base = t * SC;
    int v[SC];
    int sum = 0;
#pragma unroll
    for (int i = 0; i < SC; i++) {
        v[i] = (base + i < NN) ? g_cnt[s][base + i] : 0;
        sum += v[i];
    }
    int inc = sum;
#pragma unroll
    for (int off = 1; off < 32; off <<= 1) {
        int u = __shfl_up_sync(0xffffffffu, inc, off);
        if (lane >= off) inc += u;
    }
    __shared__ int wtot[32];
    if (lane == 31) wtot[warp] = inc;
    __syncthreads();
    if (warp == 0) {
        int w = wtot[lane];
        int wi = w;
#pragma unroll
        for (int off = 1; off < 32; off <<= 1) {
            int u = __shfl_up_sync(0xffffffffu, wi, off);
            if (lane >= off) wi += u;
        }
        wtot[lane] = wi - w;
    }
    __syncthreads();
    int run = wtot[warp] + (inc - sum);
#pragma unroll
    for (int i = 0; i < SC; i++) {
        if (base + i < NN) { g_rowptr[s][base + i] = run; g_fill[s][base + i] = run; }
        run += v[i];
    }
    if (t == 1023) g_rowptr[s][NN] = run;
}

__global__ void k_scatter(const int* __restrict__ src, const int* __restrict__ dst,
                          const float* __restrict__ vals) {
    int s   = blockIdx.y;
    int idx = blockIdx.x * blockDim.x + threadIdx.x;
    if (idx >= EE / 2) return;
    int2   s2 = *(const int2*)(src + s * EE + idx * 2);
    int2   d2 = *(const int2*)(dst + s * EE + idx * 2);
    float2 v2 = *(const float2*)(vals + s * EE + idx * 2);
    int p0 = atomicAdd(&g_fill[s][d2.x], 1);
    g_edges[s][p0] = make_int2(s2.x, __float_as_int(v2.x));
    int p1 = atomicAdd(&g_fill[s][d2.y], 1);
    g_edges[s][p1] = make_int2(s2.y, __float_as_int(v2.y));
}

// ---------------- SPMM: one warp per dst row, lane owns 4 fp16 features -------
// out = spmm(in) if ci<0 else 2*spmm(in)-c ; fp32 accumulate, fp16 store
#define GATH(srcv, vv)                                                          \
    {                                                                           \
        uint2 u = *(const uint2*)(xin + (srcv) * FF + f0);                      \
        float2 lo = __half22float2(*(__half2*)&u.x);                            \
        float2 hi = __half22float2(*(__half2*)&u.y);                            \
        ax = fmaf(vv, lo.x, ax); ay = fmaf(vv, lo.y, ay);                       \
        az = fmaf(vv, hi.x, az); aw = fmaf(vv, hi.y, aw);                       \
    }

__device__ __forceinline__ void spmm_row(int ii, int ci, int oi, int s,
                                         int gw, int lane) {
    const __half* __restrict__ xin = g_xh[ii];
    __half* __restrict__ xout      = g_xh[oi];
    int beg = g_rowptr[s][gw], end = g_rowptr[s][gw + 1];
    const int2* __restrict__ ed = g_edges[s];
    float ax = 0.f, ay = 0.f, az = 0.f, aw = 0.f;
    int e = beg;
    int f0 = lane * 4;
    if (e < end && (e & 1)) {               // peel to even e for aligned int4
        int2 e0 = ed[e];
        float v0 = __int_as_float(e0.y);
        GATH(e0.x, v0);
        e++;
    }
    for (; e + 8 <= end; e += 8) {
        int4 p0 = *(const int4*)(ed + e);
        int4 p1 = *(const int4*)(ed + e + 2);
        int4 p2 = *(const int4*)(ed + e + 4);
        int4 p3 = *(const int4*)(ed + e + 6);
        GATH(p0.x, __int_as_float(p0.y));
        GATH(p0.z, __int_as_float(p0.w));
        GATH(p1.x, __int_as_float(p1.y));
        GATH(p1.z, __int_as_float(p1.w));
        GATH(p2.x, __int_as_float(p2.y));
        GATH(p2.z, __int_as_float(p2.w));
        GATH(p3.x, __int_as_float(p3.y));
        GATH(p3.z, __int_as_float(p3.w));
    }
    for (; e < end; e++) {
        int2 e0 = ed[e];
        float v0 = __int_as_float(e0.y);
        GATH(e0.x, v0);
    }
    float rx, ry, rz, rw;
    if (ci >= 0) {
        uint2 uc = *(const uint2*)(g_xh[ci] + gw * FF + f0);
        float2 cl = __half22float2(*(__half2*)&uc.x);
        float2 ch = __half22float2(*(__half2*)&uc.y);
        rx = 2.f * ax - cl.x; ry = 2.f * ay - cl.y;
        rz = 2.f * az - ch.x; rw = 2.f * aw - ch.y;
    } else {
        rx = ax; ry = ay; rz = az; rw = aw;
    }
    __half2 r01 = __floats2half2_rn(rx, ry);
    __half2 r23 = __floats2half2_rn(rz, rw);
    uint2 uo;
    uo.x = *(unsigned*)&r01;
    uo.y = *(unsigned*)&r23;
    *(uint2*)(xout + gw * FF + f0) = uo;
}

__global__ void __launch_bounds__(256) k_spmm(int ii, int ci, int oi, int s) {
    int gw   = (blockIdx.x * blockDim.x + threadIdx.x) >> 5;
    int lane = threadIdx.x & 31;
    if (gw >= NN) return;
    spmm_row(ii, ci, oi, s, gw, lane);
}

__global__ void __launch_bounds__(256) k_spmm2(int ii0, int ci0, int oi0, int s0,
                                               int ii1, int ci1, int oi1, int s1) {
    int gw   = (blockIdx.x * blockDim.x + threadIdx.x) >> 5;
    int lane = threadIdx.x & 31;
    if (gw >= NN) return;
    if (blockIdx.y == 0) spmm_row(ii0, ci0, oi0, s0, gw, lane);
    else                 spmm_row(ii1, ci1, oi1, s1, gw, lane);
}

// ---------------- final projection: 4 rows/thread, 128 threads ----------------
// y[b,n,o] = sum_{d,m} xs[m][n][d*4+b] * W[o][d*7+m] + bias[o]
#define TNG       32
#define XPAD      132
#define GEMM_SMEM ((KK * OUTF + MM * TNG * XPAD + OUTF) * 4)   // 175,872 B

__global__ void __launch_bounds__(128) k_gemm(const float* __restrict__ W,
                                              const float* __restrict__ bias,
                                              float* __restrict__ out) {
    extern __shared__ float sm[];
    float* Wt  = sm;                        // [KK][OUTF], transposed
    float* xsm = sm + KK * OUTF;            // [MM][TNG][XPAD] (fp32)
    float* bsm = xsm + MM * TNG * XPAD;     // [OUTF]
    int tid = threadIdx.x;

    for (int idx = tid; idx < KK * OUTF / 4; idx += 128) {
        int o  = idx / (KK / 4);
        int kq = idx - o * (KK / 4);
        float4 w = *(const float4*)(W + o * KK + kq * 4);
        Wt[(kq * 4 + 0) * OUTF + o] = w.x;
        Wt[(kq * 4 + 1) * OUTF + o] = w.y;
        Wt[(kq * 4 + 2) * OUTF + o] = w.z;
        Wt[(kq * 4 + 3) * OUTF + o] = w.w;
    }
    if (tid < OUTF) bsm[tid] = bias[tid];

    int n0 = blockIdx.x * TNG;
    for (int idx = tid; idx < MM * TNG * FF / 4; idx += 128) {
        int m   = idx / (TNG * FF / 4);
        int rem = idx - m * (TNG * FF / 4);
        int nl  = rem >> 5;
        int f4  = rem & 31;
        uint2 u = *(const uint2*)(&g_xh[m][(n0 + nl) * FF + f4 * 4]);
        float2 lo = __half22float2(*(__half2*)&u.x);
        float2 hi = __half22float2(*(__half2*)&u.y);
        float4 v = make_float4(lo.x, lo.y, hi.x, hi.y);
        *(float4*)(&xsm[m * (TNG * XPAD) + nl * XPAD + f4 * 4]) = v;
    }
    __syncthreads();

    int q     = tid & 3;                    // o-group: q*16 .. q*16+15
    int rowid = tid >> 2;                   // 0..31
    int b     = rowid & 3;
    int nlb   = rowid >> 2;                 // 0..7 ; rows nlb + 8*i
    const float* xr0 = xsm + (nlb +  0) * XPAD + b;
    const float* xr1 = xsm + (nlb +  8) * XPAD + b;
    const float* xr2 = xsm + (nlb + 16) * XPAD + b;
    const float* xr3 = xsm + (nlb + 24) * XPAD + b;

    unsigned long long acc[32];             // 4 rows x 8 f32x2 pairs
#pragma unroll
    for (int j = 0; j < 32; j++) acc[j] = 0ull;

    for (int d = 0; d < DD; d++) {
#pragma unroll
        for (int m = 0; m < MM; m++) {
            int xoff = m * (TNG * XPAD) + d * 4;
            unsigned long long xp0 = pk2(xr0[xoff], xr0[xoff]);
            unsigned long long xp1 = pk2(xr1[xoff], xr1[xoff]);
            unsigned long long xp2 = pk2(xr2[xoff], xr2[xoff]);
            unsigned long long xp3 = pk2(xr3[xoff], xr3[xoff]);
            const ulonglong2* w2 = (const ulonglong2*)(Wt + (d * MM + m) * OUTF + q * 16);
            ulonglong2 wa = w2[0], wb = w2[1], wc = w2[2], wd = w2[3];
            acc[0]  = ffma2(xp0, wa.x, acc[0]);  acc[1]  = ffma2(xp0, wa.y, acc[1]);
            acc[2]  = ffma2(xp0, wb.x, acc[2]);  acc[3]  = ffma2(xp0, wb.y, acc[3]);
            acc[4]  = ffma2(xp0, wc.x, acc[4]);  acc[5]  = ffma2(xp0, wc.y, acc[5]);
            acc[6]  = ffma2(xp0, wd.x, acc[6]);  acc[7]  = ffma2(xp0, wd.y, acc[7]);
            acc[8]  = ffma2(xp1, wa.x, acc[8]);  acc[9]  = ffma2(xp1, wa.y, acc[9]);
            acc[10] = ffma2(xp1, wb.x, acc[10]); acc[11] = ffma2(xp1, wb.y, acc[11]);
            acc[12] = ffma2(xp1, wc.x, acc[12]); acc[13] = ffma2(xp1, wc.y, acc[13]);
            acc[14] = ffma2(xp1, wd.x, acc[14]); acc[15] = ffma2(xp1, wd.y, acc[15]);
            acc[16] = ffma2(xp2, wa.x, acc[16]); acc[17] = ffma2(xp2, wa.y, acc[17]);
            acc[18] = ffma2(xp2, wb.x, acc[18]); acc[19] = ffma2(xp2, wb.y, acc[19]);
            acc[20] = ffma2(xp2, wc.x, acc[20]); acc[21] = ffma2(xp2, wc.y, acc[21]);
            acc[22] = ffma2(xp2, wd.x, acc[22]); acc[23] = ffma2(xp2, wd.y, acc[23]);
            acc[24] = ffma2(xp3, wa.x, acc[24]); acc[25] = ffma2(xp3, wa.y, acc[25]);
            acc[26] = ffma2(xp3, wb.x, acc[26]); acc[27] = ffma2(xp3, wb.y, acc[27]);
            acc[28] = ffma2(xp3, wc.x, acc[28]); acc[29] = ffma2(xp3, wc.y, acc[29]);
            acc[30] = ffma2(xp3, wd.x, acc[30]); acc[31] = ffma2(xp3, wd.y, acc[31]);
        }
    }

#pragma unroll
    for (int i = 0; i < 4; i++) {
        int n = n0 + nlb + 8 * i;
        float* op = out + ((size_t)b * NN + n) * OUTF + q * 16;
#pragma unroll
        for (int j = 0; j < 4; j++) {
            float a0, a1, a2, a3;
            upk2(a0, a1, acc[i * 8 + j * 2]);
            upk2(a2, a3, acc[i * 8 + j * 2 + 1]);
            float4 o4;
            o4.x = a0 + bsm[q * 16 + j * 4 + 0];
            o4.y = a1 + bsm[q * 16 + j * 4 + 1];
            o4.z = a2 + bsm[q * 16 + j * 4 + 2];
            o4.w = a3 + bsm[q * 16 + j * 4 + 3];
            *(float4*)(op + j * 4) = o4;
        }
    }
}

// ---------------- launch ----------------
extern "C" void kernel_launch(void* const* d_in, const int* in_sizes, int n_in,
                              void* d_out, int out_size) {
    const float* inputs = (const float*)d_in[0];
    const float* evals  = (const float*)d_in[1];
    const float* W      = (const float*)d_in[2];
    const float* bias   = (const float*)d_in[3];
    const int*   esrc   = (const int*)d_in[4];
    const int*   edst   = (const int*)d_in[5];
    float* out = (float*)d_out;

    // x0 build (fp16) + counter zero (fused)
    k_prep<<<(NN * DD + 255) / 256, 256>>>(inputs);

    // dense CSR build for both supports (2 edges/thread)
    dim3 ge((EE / 2 + 255) / 256, SS);
    k_hist<<<ge, 256>>>(edst);
    k_scan<<<SS, 1024>>>();
    k_scatter<<<ge, 256>>>(esrc, edst, evals);

    // Chebyshev recurrence (faithful to reference aliasing)
    const int spmm_grid = (NN * 32 + 255) / 256;   // 1 warp per row
    k_spmm<<<spmm_grid, 256>>>(0, -1, 1, 0);                 // xs1 = A0 x0
    k_spmm<<<spmm_grid, 256>>>(1,  0, 2, 0);                 // xs2 = 2 A0 xs1 - xs0
    dim3 gd(spmm_grid, 2);
    k_spmm2<<<gd, 256>>>(2, 1, 3, 0,   2, -1, 4, 1);         // xs3 ∥ xs4
    k_spmm<<<spmm_grid, 256>>>(4,  2, 5, 1);                 // xs5 = 2 A1 xs4 - xs2
    k_spmm<<<spmm_grid, 256>>>(5,  4, 6, 1);                 // xs6 = 2 A1 xs5 - xs4

    // projection (4 rows/thread, 128 threads)
    cudaFuncSetAttribute(k_gemm, cudaFuncAttributeMaxDynamicSharedMemorySize, GEMM_SMEM);
    k_gemm<<<NN / TNG, 128, GEMM_SMEM>>>(W, bias, out);
}